// round 13
// baseline (speedup 1.0000x reference)
#include <cuda_runtime.h>

// 3x3 VALID conv, 8192x8192 fp32 in -> 8190x8190 fp32 out, + scalar bias.
// R8 (90.6us, DRAM 76.4%) is the best config; R10/R11 proved occ/slack tuning
// is plateaued -> binder is achieved HBM efficiency on the mixed R/W stream.
// R12 = R8 + cache-policy hints: __stcs on output (write-once, keep out of
// L2) and __ldcs on input (near-zero cross-block reuse). Zero structural
// change; targets DRAM burst efficiency / L2 pollution only.

#define IW 8192
#define OW 8190
#define OH 8190
#define RPT 16   // output rows per thread; even -> row parity == iter parity
#define TPB 128  // threads/block; 4 cols/thread -> 512 cols/block

__global__ __launch_bounds__(TPB, 12) void Conv2D_35210141892837_kernel(
    const float* __restrict__ x,
    const float* __restrict__ wgt,
    const float* __restrict__ bias,
    float* __restrict__ out)
{
    const int c  = (blockIdx.x * TPB + threadIdx.x) * 4;   // 0..8188
    const int r0 = blockIdx.y * RPT;                       // even
    if (c >= OW) return;

    const float w00 = wgt[0], w01 = wgt[1], w02 = wgt[2];
    const float w10 = wgt[3], w11 = wgt[4], w12 = wgt[5];
    const float w20 = wgt[6], w21 = wgt[7], w22 = wgt[8];
    const float bv  = bias[0];

    // ---- single edge thread per y-block (c == 8188):
    //      even rows: cols 8188,8189 ; odd rows: cols 0,1 ----
    if (c == 8188) {
        for (int i = 0; i < RPT; i++) {
            const int r = r0 + i;
            if (r >= OH) break;
            const size_t base = (size_t)r * IW + ((r & 1) ? 0 : 8188);
            float4 t = __ldcs((const float4*)(x + base));
            float4 m = __ldcs((const float4*)(x + base + IW));
            float4 l = __ldcs((const float4*)(x + base + 2 * IW));
            float o0 = bv, o1 = bv;
            o0 = fmaf(w00, t.x, o0); o0 = fmaf(w01, t.y, o0); o0 = fmaf(w02, t.z, o0);
            o0 = fmaf(w10, m.x, o0); o0 = fmaf(w11, m.y, o0); o0 = fmaf(w12, m.z, o0);
            o0 = fmaf(w20, l.x, o0); o0 = fmaf(w21, l.y, o0); o0 = fmaf(w22, l.z, o0);
            o1 = fmaf(w00, t.y, o1); o1 = fmaf(w01, t.z, o1); o1 = fmaf(w02, t.w, o1);
            o1 = fmaf(w10, m.y, o1); o1 = fmaf(w11, m.z, o1); o1 = fmaf(w12, m.w, o1);
            o1 = fmaf(w20, l.y, o1); o1 = fmaf(w21, l.z, o1); o1 = fmaf(w22, l.w, o1);
            float* po = out + (size_t)r * OW + ((r & 1) ? 0 : 8188);
            __stcs((float2*)po, make_float2(o0, o1));
        }
        return;
    }

    // ---- main path: c in [0, 8184]; loads cols c..c+7 (in-bounds).
    //      Even out-rows: window shift s=0; odd: s=2 -> 16B-aligned STG.128.
    float buf[3][8];

    auto load8 = [&](int rr, float* d) {
        const float* p = x + (size_t)rr * IW + c;
        float4 a = __ldcs((const float4*)(p));
        float4 b = __ldcs((const float4*)(p + 4));
        d[0]=a.x; d[1]=a.y; d[2]=a.z; d[3]=a.w;
        d[4]=b.x; d[5]=b.y; d[6]=b.z; d[7]=b.w;
    };

    load8(r0,     buf[0]);
    load8(r0 + 1, buf[1]);

    const bool row_full = (r0 + RPT <= OH);

    #pragma unroll
    for (int i = 0; i < RPT; i++) {
        const int r = r0 + i;
        if (!row_full && r >= OH) break;
        load8(r + 2, buf[(i + 2) % 3]);                // r+2 <= 8191

        const float* t = buf[ i      % 3];
        const float* m = buf[(i + 1) % 3];
        const float* l = buf[(i + 2) % 3];

        const int s = (i & 1) ? 2 : 0;                 // compile-time per iter

        float o0 = bv, o1 = bv, o2 = bv, o3 = bv;
        o0 = fmaf(w00, t[s+0], o0); o0 = fmaf(w01, t[s+1], o0); o0 = fmaf(w02, t[s+2], o0);
        o0 = fmaf(w10, m[s+0], o0); o0 = fmaf(w11, m[s+1], o0); o0 = fmaf(w12, m[s+2], o0);
        o0 = fmaf(w20, l[s+0], o0); o0 = fmaf(w21, l[s+1], o0); o0 = fmaf(w22, l[s+2], o0);
        o1 = fmaf(w00, t[s+1], o1); o1 = fmaf(w01, t[s+2], o1); o1 = fmaf(w02, t[s+3], o1);
        o1 = fmaf(w10, m[s+1], o1); o1 = fmaf(w11, m[s+2], o1); o1 = fmaf(w12, m[s+3], o1);
        o1 = fmaf(w20, l[s+1], o1); o1 = fmaf(w21, l[s+2], o1); o1 = fmaf(w22, l[s+3], o1);
        o2 = fmaf(w00, t[s+2], o2); o2 = fmaf(w01, t[s+3], o2); o2 = fmaf(w02, t[s+4], o2);
        o2 = fmaf(w10, m[s+2], o2); o2 = fmaf(w11, m[s+3], o2); o2 = fmaf(w12, m[s+4], o2);
        o2 = fmaf(w20, l[s+2], o2); o2 = fmaf(w21, l[s+3], o2); o2 = fmaf(w22, l[s+4], o2);
        o3 = fmaf(w00, t[s+3], o3); o3 = fmaf(w01, t[s+4], o3); o3 = fmaf(w02, t[s+5], o3);
        o3 = fmaf(w10, m[s+3], o3); o3 = fmaf(w11, m[s+4], o3); o3 = fmaf(w12, m[s+5], o3);
        o3 = fmaf(w20, l[s+3], o3); o3 = fmaf(w21, l[s+4], o3); o3 = fmaf(w22, l[s+5], o3);

        // (r*8190 + c + s) % 4 == 0 for both parities -> 16B-aligned STG.128.
        __stcs((float4*)(out + (size_t)r * OW + c + s),
               make_float4(o0, o1, o2, o3));

        if (s == 2 && c == 0) {
            // Odd rows: cols 0,1 not covered by shifted windows.
            float e0 = bv, e1 = bv;
            e0 = fmaf(w00, t[0], e0); e0 = fmaf(w01, t[1], e0); e0 = fmaf(w02, t[2], e0);
            e0 = fmaf(w10, m[0], e0); e0 = fmaf(w11, m[1], e0); e0 = fmaf(w12, m[2], e0);
            e0 = fmaf(w20, l[0], e0); e0 = fmaf(w21, l[1], e0); e0 = fmaf(w22, l[2], e0);
            e1 = fmaf(w00, t[1], e1); e1 = fmaf(w01, t[2], e1); e1 = fmaf(w02, t[3], e1);
            e1 = fmaf(w10, m[1], e1); e1 = fmaf(w11, m[2], e1); e1 = fmaf(w12, m[3], e1);
            e1 = fmaf(w20, l[1], e1); e1 = fmaf(w21, l[2], e1); e1 = fmaf(w22, l[3], e1);
            __stcs((float2*)(out + (size_t)r * OW), make_float2(e0, e1));
        }
    }
}

extern "C" void kernel_launch(void* const* d_in, const int* in_sizes, int n_in,
                              void* d_out, int out_size) {
    const float* x    = (const float*)d_in[0];
    const float* wgt  = (const float*)d_in[1];
    const float* bias = (const float*)d_in[2];
    float* out = (float*)d_out;

    dim3 block(TPB, 1, 1);
    dim3 grid((OW + TPB * 4 - 1) / (TPB * 4),   // 16
              (OH + RPT - 1) / RPT,             // 512
              1);
    Conv2D_35210141892837_kernel<<<grid, block>>>(x, wgt, bias, out);
}

// round 14
// speedup vs baseline: 1.0743x; 1.0743x over previous
#include <cuda_runtime.h>

// 3x3 VALID conv, 8192x8192 fp32 in -> 8190x8190 fp32 out, + scalar bias.
// R8 (90.6us, DRAM 76.4%): parity-shifted aligned STG.128, 4 cols/thread.
// R12 (__ldcs+__stcs) regressed: .cs loads evicted the 2-row halo that L2
// was serving between adjacent y-blocks (+15MB DRAM traffic). R13 isolates
// the store side: default-cached loads (R8 exact) + __stcs ONLY on stores
// (output is write-once; streaming stores free L2 for the input halo).

#define IW 8192
#define OW 8190
#define OH 8190
#define RPT 16   // output rows per thread; even -> row parity == iter parity
#define TPB 128  // threads/block; 4 cols/thread -> 512 cols/block

__global__ __launch_bounds__(TPB, 12) void Conv2D_35210141892837_kernel(
    const float* __restrict__ x,
    const float* __restrict__ wgt,
    const float* __restrict__ bias,
    float* __restrict__ out)
{
    const int c  = (blockIdx.x * TPB + threadIdx.x) * 4;   // 0..8188
    const int r0 = blockIdx.y * RPT;                       // even
    if (c >= OW) return;

    const float w00 = wgt[0], w01 = wgt[1], w02 = wgt[2];
    const float w10 = wgt[3], w11 = wgt[4], w12 = wgt[5];
    const float w20 = wgt[6], w21 = wgt[7], w22 = wgt[8];
    const float bv  = bias[0];

    // ---- single edge thread per y-block (c == 8188):
    //      even rows: cols 8188,8189 ; odd rows: cols 0,1 ----
    if (c == 8188) {
        for (int i = 0; i < RPT; i++) {
            const int r = r0 + i;
            if (r >= OH) break;
            const size_t base = (size_t)r * IW + ((r & 1) ? 0 : 8188);
            float4 t = *(const float4*)(x + base);
            float4 m = *(const float4*)(x + base + IW);
            float4 l = *(const float4*)(x + base + 2 * IW);
            float o0 = bv, o1 = bv;
            o0 = fmaf(w00, t.x, o0); o0 = fmaf(w01, t.y, o0); o0 = fmaf(w02, t.z, o0);
            o0 = fmaf(w10, m.x, o0); o0 = fmaf(w11, m.y, o0); o0 = fmaf(w12, m.z, o0);
            o0 = fmaf(w20, l.x, o0); o0 = fmaf(w21, l.y, o0); o0 = fmaf(w22, l.z, o0);
            o1 = fmaf(w00, t.y, o1); o1 = fmaf(w01, t.z, o1); o1 = fmaf(w02, t.w, o1);
            o1 = fmaf(w10, m.y, o1); o1 = fmaf(w11, m.z, o1); o1 = fmaf(w12, m.w, o1);
            o1 = fmaf(w20, l.y, o1); o1 = fmaf(w21, l.z, o1); o1 = fmaf(w22, l.w, o1);
            float* po = out + (size_t)r * OW + ((r & 1) ? 0 : 8188);
            __stcs((float2*)po, make_float2(o0, o1));
        }
        return;
    }

    // ---- main path: c in [0, 8184]; loads cols c..c+7 (in-bounds).
    //      Even out-rows: window shift s=0; odd: s=2 -> 16B-aligned STG.128.
    float buf[3][8];

    auto load8 = [&](int rr, float* d) {
        const float* p = x + (size_t)rr * IW + c;
        float4 a = *(const float4*)(p);
        float4 b = *(const float4*)(p + 4);
        d[0]=a.x; d[1]=a.y; d[2]=a.z; d[3]=a.w;
        d[4]=b.x; d[5]=b.y; d[6]=b.z; d[7]=b.w;
    };

    load8(r0,     buf[0]);
    load8(r0 + 1, buf[1]);

    const bool row_full = (r0 + RPT <= OH);

    #pragma unroll
    for (int i = 0; i < RPT; i++) {
        const int r = r0 + i;
        if (!row_full && r >= OH) break;
        load8(r + 2, buf[(i + 2) % 3]);                // r+2 <= 8191

        const float* t = buf[ i      % 3];
        const float* m = buf[(i + 1) % 3];
        const float* l = buf[(i + 2) % 3];

        const int s = (i & 1) ? 2 : 0;                 // compile-time per iter

        float o0 = bv, o1 = bv, o2 = bv, o3 = bv;
        o0 = fmaf(w00, t[s+0], o0); o0 = fmaf(w01, t[s+1], o0); o0 = fmaf(w02, t[s+2], o0);
        o0 = fmaf(w10, m[s+0], o0); o0 = fmaf(w11, m[s+1], o0); o0 = fmaf(w12, m[s+2], o0);
        o0 = fmaf(w20, l[s+0], o0); o0 = fmaf(w21, l[s+1], o0); o0 = fmaf(w22, l[s+2], o0);
        o1 = fmaf(w00, t[s+1], o1); o1 = fmaf(w01, t[s+2], o1); o1 = fmaf(w02, t[s+3], o1);
        o1 = fmaf(w10, m[s+1], o1); o1 = fmaf(w11, m[s+2], o1); o1 = fmaf(w12, m[s+3], o1);
        o1 = fmaf(w20, l[s+1], o1); o1 = fmaf(w21, l[s+2], o1); o1 = fmaf(w22, l[s+3], o1);
        o2 = fmaf(w00, t[s+2], o2); o2 = fmaf(w01, t[s+3], o2); o2 = fmaf(w02, t[s+4], o2);
        o2 = fmaf(w10, m[s+2], o2); o2 = fmaf(w11, m[s+3], o2); o2 = fmaf(w12, m[s+4], o2);
        o2 = fmaf(w20, l[s+2], o2); o2 = fmaf(w21, l[s+3], o2); o2 = fmaf(w22, l[s+4], o2);
        o3 = fmaf(w00, t[s+3], o3); o3 = fmaf(w01, t[s+4], o3); o3 = fmaf(w02, t[s+5], o3);
        o3 = fmaf(w10, m[s+3], o3); o3 = fmaf(w11, m[s+4], o3); o3 = fmaf(w12, m[s+5], o3);
        o3 = fmaf(w20, l[s+3], o3); o3 = fmaf(w21, l[s+4], o3); o3 = fmaf(w22, l[s+5], o3);

        // (r*8190 + c + s) % 4 == 0 for both parities -> 16B-aligned STG.128.
        __stcs((float4*)(out + (size_t)r * OW + c + s),
               make_float4(o0, o1, o2, o3));

        if (s == 2 && c == 0) {
            // Odd rows: cols 0,1 not covered by shifted windows.
            float e0 = bv, e1 = bv;
            e0 = fmaf(w00, t[0], e0); e0 = fmaf(w01, t[1], e0); e0 = fmaf(w02, t[2], e0);
            e0 = fmaf(w10, m[0], e0); e0 = fmaf(w11, m[1], e0); e0 = fmaf(w12, m[2], e0);
            e0 = fmaf(w20, l[0], e0); e0 = fmaf(w21, l[1], e0); e0 = fmaf(w22, l[2], e0);
            e1 = fmaf(w00, t[1], e1); e1 = fmaf(w01, t[2], e1); e1 = fmaf(w02, t[3], e1);
            e1 = fmaf(w10, m[1], e1); e1 = fmaf(w11, m[2], e1); e1 = fmaf(w12, m[3], e1);
            e1 = fmaf(w20, l[1], e1); e1 = fmaf(w21, l[2], e1); e1 = fmaf(w22, l[3], e1);
            __stcs((float2*)(out + (size_t)r * OW), make_float2(e0, e1));
        }
    }
}

extern "C" void kernel_launch(void* const* d_in, const int* in_sizes, int n_in,
                              void* d_out, int out_size) {
    const float* x    = (const float*)d_in[0];
    const float* wgt  = (const float*)d_in[1];
    const float* bias = (const float*)d_in[2];
    float* out = (float*)d_out;

    dim3 block(TPB, 1, 1);
    dim3 grid((OW + TPB * 4 - 1) / (TPB * 4),   // 16
              (OH + RPT - 1) / RPT,             // 512
              1);
    Conv2D_35210141892837_kernel<<<grid, block>>>(x, wgt, bias, out);
}